// round 2
// baseline (speedup 1.0000x reference)
#include <cuda_runtime.h>
#include <cuda_bf16.h>
#include <math.h>

// ---------------- problem constants ----------------
#define T_TYPES 4
#define R_RELS 6
#define HID 64
#define HEADS 8
#define DH 8
#define LAYERS 2
#define OUT_DIM 4

static const int N_[T_TYPES]   = {100000, 200000, 20000, 2000};
static const int F_[T_TYPES]   = {334, 512, 128, 128};
static const int OFF_[T_TYPES] = {0, 100000, 300000, 320000};
#define NTOT 322000
static const int E_[R_RELS]  = {800000, 800000, 1000000, 1000000, 200000, 200000};
static const int RS_[R_RELS] = {0, 1, 1, 2, 1, 3};   // src type
static const int RD_[R_RELS] = {1, 0, 2, 1, 3, 1};   // dst type
#define EMAX 1000000
#define NDMAX 200000

// ---------------- device scratch (static, no allocation) ----------------
__device__ float    g_h[NTOT * HID];
__device__ float    g_K[NTOT * HID];
__device__ float    g_Q[NTOT * HID];
__device__ float    g_V[NTOT * HID];
__device__ float    g_out[NTOT * HID];
__device__ float    g_acc[NDMAX * HID];       // per-relation message accumulator / adapter tmp
__device__ float    g_den[NDMAX * HEADS];
__device__ unsigned g_m[NDMAX * HEADS];       // ordered-uint encoded running max
__device__ float    g_sc[EMAX * HEADS];       // per-edge scores scratch

// ---------------- helpers ----------------
__device__ __forceinline__ unsigned fOrd(float f) {
    unsigned u = __float_as_uint(f);
    return (u & 0x80000000u) ? ~u : (u | 0x80000000u);
}
__device__ __forceinline__ float ordF(unsigned u) {
    return (u & 0x80000000u) ? __uint_as_float(u ^ 0x80000000u) : __uint_as_float(~u);
}
#define ORD_NEG_INF 0x007FFFFFu   // fOrd(-inf)

__device__ __forceinline__ float gelu_exact(float x) {
    return 0.5f * x * (1.0f + erff(x * 0.70710678118654752f));
}

// ---------------- fill kernels ----------------
__global__ void fill_f32(float* p, float v, int n) {
    int i = blockIdx.x * blockDim.x + threadIdx.x;
    if (i < n) p[i] = v;
}
__global__ void fill_u32(unsigned* p, unsigned v, int n) {
    int i = blockIdx.x * blockDim.x + threadIdx.x;
    if (i < n) p[i] = v;
}

// ---------------- tiled GEMM: Y[M,64] = act_out(act_in(X)[M,K] @ W[K,64] + B) ----------------
// ACT_IN: 0=none, 1=gelu on X elements. ACT_OUT: 0=none, 1=relu.
template <int ACT_IN, int ACT_OUT>
__global__ void gemm64_kernel(const float* __restrict__ X, const float* __restrict__ W,
                              const float* __restrict__ B, float* __restrict__ Y,
                              int M, int K) {
    __shared__ float xs[64][33];
    __shared__ float ws[32][64];
    int tid = threadIdx.x;
    int tx = tid & 15, ty = tid >> 4;
    int rowBase = blockIdx.x * 64;
    float acc[4][4] = {};
    for (int k0 = 0; k0 < K; k0 += 32) {
        #pragma unroll
        for (int it = 0; it < 8; it++) {
            int idx = tid + it * 256;
            int r = idx >> 5, c = idx & 31;
            int gr = rowBase + r, gc = k0 + c;
            float v = 0.0f;
            if (gr < M && gc < K) {
                v = X[(size_t)gr * K + gc];
                if (ACT_IN == 1) v = gelu_exact(v);
            }
            xs[r][c] = v;
        }
        #pragma unroll
        for (int it = 0; it < 8; it++) {
            int idx = tid + it * 256;
            int kk = idx >> 6, c = idx & 63;
            int gk = k0 + kk;
            ws[kk][c] = (gk < K) ? W[(size_t)gk * 64 + c] : 0.0f;
        }
        __syncthreads();
        #pragma unroll
        for (int kk = 0; kk < 32; kk++) {
            float a[4], b[4];
            #pragma unroll
            for (int i = 0; i < 4; i++) a[i] = xs[ty + 16 * i][kk];
            #pragma unroll
            for (int j = 0; j < 4; j++) b[j] = ws[kk][tx + 16 * j];
            #pragma unroll
            for (int i = 0; i < 4; i++)
                #pragma unroll
                for (int j = 0; j < 4; j++)
                    acc[i][j] += a[i] * b[j];
        }
        __syncthreads();
    }
    #pragma unroll
    for (int i = 0; i < 4; i++) {
        int gr = rowBase + ty + 16 * i;
        if (gr >= M) continue;
        #pragma unroll
        for (int j = 0; j < 4; j++) {
            int col = tx + 16 * j;
            float v = acc[i][j] + B[col];
            if (ACT_OUT == 1) v = fmaxf(v, 0.0f);
            Y[(size_t)gr * 64 + col] = v;
        }
    }
}

// ---------------- edge pass A: scores + segment max ----------------
// one thread per (edge, head); 32 edges per 256-thread block
__global__ void edge_scores_kernel(const int* __restrict__ src, const int* __restrict__ dst,
                                   const float* __restrict__ K, const float* __restrict__ Q,
                                   const float* __restrict__ Arel, const float* __restrict__ Prel,
                                   float* __restrict__ scores, unsigned* __restrict__ mEnc,
                                   int E) {
    __shared__ float As[512];   // transposed: [d][f][h]
    __shared__ float Ps[8];
    int tid = threadIdx.x;
    #pragma unroll
    for (int it = 0; it < 2; it++) {
        int i = tid + it * 256;
        int h = i >> 6, d = (i >> 3) & 7, f = i & 7;
        As[d * 64 + f * 8 + h] = Arel[i];
    }
    if (tid < 8) Ps[tid] = Prel[tid];
    __syncthreads();

    int e = blockIdx.x * 32 + (tid >> 3);
    int h = tid & 7;
    if (e >= E) return;
    int s = src[e], dd = dst[e];

    const float4* kp = (const float4*)(K + (size_t)s * 64 + h * 8);
    float4 k0 = kp[0], k1 = kp[1];
    const float4* qp = (const float4*)(Q + (size_t)dd * 64 + h * 8);
    float4 q0 = qp[0], q1 = qp[1];
    float kin[8] = {k0.x, k0.y, k0.z, k0.w, k1.x, k1.y, k1.z, k1.w};
    float qin[8] = {q0.x, q0.y, q0.z, q0.w, q1.x, q1.y, q1.z, q1.w};

    float sc = 0.0f;
    #pragma unroll
    for (int f = 0; f < 8; f++) {
        float kf = 0.0f;
        #pragma unroll
        for (int d2 = 0; d2 < 8; d2++) kf += kin[d2] * As[d2 * 64 + f * 8 + h];
        sc += qin[f] * kf;
    }
    sc *= Ps[h] * 0.35355339059327373f;   // 1/sqrt(DH)
    scores[(size_t)e * 8 + h] = sc;
    atomicMax(&mEnc[(size_t)dd * 8 + h], fOrd(sc));
}

// ---------------- edge pass B: exp / denom / weighted message accumulate ----------------
__global__ void edge_accum_kernel(const int* __restrict__ src, const int* __restrict__ dst,
                                  const float* __restrict__ V, const float* __restrict__ Mrel,
                                  const float* __restrict__ scores, const unsigned* __restrict__ mEnc,
                                  float* __restrict__ den, float* __restrict__ acc,
                                  int E) {
    __shared__ float Ms[512];   // transposed: [d][f][h]
    int tid = threadIdx.x;
    #pragma unroll
    for (int it = 0; it < 2; it++) {
        int i = tid + it * 256;
        int h = i >> 6, d = (i >> 3) & 7, f = i & 7;
        Ms[d * 64 + f * 8 + h] = Mrel[i];
    }
    __syncthreads();

    int e = blockIdx.x * 32 + (tid >> 3);
    int h = tid & 7;
    if (e >= E) return;
    int s = src[e], dd = dst[e];

    const float4* vp = (const float4*)(V + (size_t)s * 64 + h * 8);
    float4 v0 = vp[0], v1 = vp[1];
    float vin[8] = {v0.x, v0.y, v0.z, v0.w, v1.x, v1.y, v1.z, v1.w};

    float sc = scores[(size_t)e * 8 + h];
    float m = ordF(mEnc[(size_t)dd * 8 + h]);
    float ex = expf(sc - m);

    atomicAdd(&den[(size_t)dd * 8 + h], ex);
    float* ap = acc + (size_t)dd * 64 + h * 8;
    #pragma unroll
    for (int f = 0; f < 8; f++) {
        float vf = 0.0f;
        #pragma unroll
        for (int d2 = 0; d2 < 8; d2++) vf += vin[d2] * Ms[d2 * 64 + f * 8 + h];
        atomicAdd(&ap[f], vf * ex);
    }
}

// ---------------- pass C: normalize and add into destination accumulator ----------------
__global__ void finalize_kernel(float* __restrict__ out, const float* __restrict__ acc,
                                const float* __restrict__ den, int n /* = Nd*64 */) {
    int i = blockIdx.x * blockDim.x + threadIdx.x;
    if (i >= n) return;
    int node = i >> 6;
    int h = (i >> 3) & 7;
    float d = den[node * 8 + h];
    if (d > 0.0f) out[i] += acc[i] / d;
}

// ---------------- residual gate: h = g*o + (1-g)*h ----------------
__global__ void combine_kernel(float* __restrict__ h, const float* __restrict__ o,
                               const float* __restrict__ skip, int skipIdx, int n) {
    int i = blockIdx.x * blockDim.x + threadIdx.x;
    if (i >= n) return;
    float g = 1.0f / (1.0f + expf(-skip[skipIdx]));
    h[i] = g * o[i] + (1.0f - g) * h[i];
}

// ---------------- final head: logits = h_author @ W_out + b_out ----------------
__global__ void out_kernel(const float* __restrict__ h, const float* __restrict__ Wo,
                           const float* __restrict__ bo, float* __restrict__ y, int n) {
    __shared__ float ws[256];
    __shared__ float bs[4];
    if (threadIdx.x < 256) ws[threadIdx.x] = Wo[threadIdx.x];
    if (threadIdx.x < 4) bs[threadIdx.x] = bo[threadIdx.x];
    __syncthreads();
    int node = blockIdx.x * blockDim.x + threadIdx.x;
    if (node >= n) return;
    const float4* hp = (const float4*)(h + (size_t)node * 64);
    float a0 = bs[0], a1 = bs[1], a2 = bs[2], a3 = bs[3];
    #pragma unroll
    for (int i = 0; i < 16; i++) {
        float4 hv = hp[i];
        const float* w = ws + 4 * i * 4;
        a0 += hv.x * w[0]  + hv.y * w[4]  + hv.z * w[8]  + hv.w * w[12];
        a1 += hv.x * w[1]  + hv.y * w[5]  + hv.z * w[9]  + hv.w * w[13];
        a2 += hv.x * w[2]  + hv.y * w[6]  + hv.z * w[10] + hv.w * w[14];
        a3 += hv.x * w[3]  + hv.y * w[7]  + hv.z * w[11] + hv.w * w[15];
    }
    float4 r = make_float4(a0, a1, a2, a3);
    ((float4*)y)[node] = r;
}

// ---------------- host launcher ----------------
static inline int cdiv(int a, int b) { return (a + b - 1) / b; }

extern "C" void kernel_launch(void* const* d_in, const int* in_sizes, int n_in,
                              void* d_out, int out_size) {
    (void)n_in; (void)out_size;

    const float* x[T_TYPES]   = {(const float*)d_in[0], (const float*)d_in[1],
                                 (const float*)d_in[2], (const float*)d_in[3]};
    const float* Win[T_TYPES] = {(const float*)d_in[4], (const float*)d_in[6],
                                 (const float*)d_in[8], (const float*)d_in[10]};
    const float* bin[T_TYPES] = {(const float*)d_in[5], (const float*)d_in[7],
                                 (const float*)d_in[9], (const float*)d_in[11]};

    // Weight block ordering is ambiguous between the setup_inputs() dict order
    // (KW,QW,VW,AW, Kb,Qb,Vb,Ab) and the reference() signature order
    // (KW,Kb,QW,Qb,VW,Vb,AW,Ab). Disambiguate with in_sizes[13]:
    //   dict order      -> index 13 is QW  (2*4*64*64 = 32768 elements)
    //   signature order -> index 13 is Kb  (2*4*64   = 512 elements)
    const float *KW, *Kb, *QW, *Qb, *VW, *Vb, *AW, *Ab;
    if (in_sizes[13] > 4096) {
        KW = (const float*)d_in[12];
        QW = (const float*)d_in[13];
        VW = (const float*)d_in[14];
        AW = (const float*)d_in[15];
        Kb = (const float*)d_in[16];
        Qb = (const float*)d_in[17];
        Vb = (const float*)d_in[18];
        Ab = (const float*)d_in[19];
    } else {
        KW = (const float*)d_in[12];
        Kb = (const float*)d_in[13];
        QW = (const float*)d_in[14];
        Qb = (const float*)d_in[15];
        VW = (const float*)d_in[16];
        Vb = (const float*)d_in[17];
        AW = (const float*)d_in[18];
        Ab = (const float*)d_in[19];
    }
    const float* skip  = (const float*)d_in[20];
    const float* A_rel = (const float*)d_in[21];
    const float* M_rel = (const float*)d_in[22];
    const float* P_rel = (const float*)d_in[23];
    const float* W_out = (const float*)d_in[24];
    const float* b_out = (const float*)d_in[25];
    const int* ei[R_RELS] = {(const int*)d_in[26], (const int*)d_in[27], (const int*)d_in[28],
                             (const int*)d_in[29], (const int*)d_in[30], (const int*)d_in[31]};

    float *hB, *kB, *qB, *vB, *oB, *accB, *denB, *scB;
    unsigned* mB;
    cudaGetSymbolAddress((void**)&hB,   g_h);
    cudaGetSymbolAddress((void**)&kB,   g_K);
    cudaGetSymbolAddress((void**)&qB,   g_Q);
    cudaGetSymbolAddress((void**)&vB,   g_V);
    cudaGetSymbolAddress((void**)&oB,   g_out);
    cudaGetSymbolAddress((void**)&accB, g_acc);
    cudaGetSymbolAddress((void**)&denB, g_den);
    cudaGetSymbolAddress((void**)&mB,   g_m);
    cudaGetSymbolAddress((void**)&scB,  g_sc);

    // ---- input projections: h[t] = relu(x @ W_in + b) ----
    for (int t = 0; t < T_TYPES; t++) {
        gemm64_kernel<0, 1><<<cdiv(N_[t], 64), 256>>>(
            x[t], Win[t], bin[t], hB + (size_t)OFF_[t] * HID, N_[t], F_[t]);
    }

    for (int l = 0; l < LAYERS; l++) {
        // zero attention output accumulator
        fill_f32<<<cdiv(NTOT * HID, 256), 256>>>(oB, 0.0f, NTOT * HID);

        // K/Q/V projections per type
        for (int t = 0; t < T_TYPES; t++) {
            int base = l * T_TYPES + t;
            float* dsth = hB + (size_t)OFF_[t] * HID;
            gemm64_kernel<0, 0><<<cdiv(N_[t], 64), 256>>>(
                dsth, KW + (size_t)base * 4096, Kb + (size_t)base * 64,
                kB + (size_t)OFF_[t] * HID, N_[t], HID);
            gemm64_kernel<0, 0><<<cdiv(N_[t], 64), 256>>>(
                dsth, QW + (size_t)base * 4096, Qb + (size_t)base * 64,
                qB + (size_t)OFF_[t] * HID, N_[t], HID);
            gemm64_kernel<0, 0><<<cdiv(N_[t], 64), 256>>>(
                dsth, VW + (size_t)base * 4096, Vb + (size_t)base * 64,
                vB + (size_t)OFF_[t] * HID, N_[t], HID);
        }

        // relations
        for (int r = 0; r < R_RELS; r++) {
            int s = RS_[r], d = RD_[r];
            int Nd = N_[d], E = E_[r];
            const int* srcIdx = ei[r];
            const int* dstIdx = ei[r] + E;
            int relBase = l * R_RELS + r;

            fill_u32<<<cdiv(Nd * HEADS, 256), 256>>>(mB, ORD_NEG_INF, Nd * HEADS);
            fill_f32<<<cdiv(Nd * HEADS, 256), 256>>>(denB, 0.0f, Nd * HEADS);
            fill_f32<<<cdiv(Nd * HID, 256), 256>>>(accB, 0.0f, Nd * HID);

            edge_scores_kernel<<<cdiv(E, 32), 256>>>(
                srcIdx, dstIdx,
                kB + (size_t)OFF_[s] * HID, qB + (size_t)OFF_[d] * HID,
                A_rel + (size_t)relBase * 512, P_rel + (size_t)relBase * 8,
                scB, mB, E);

            edge_accum_kernel<<<cdiv(E, 32), 256>>>(
                srcIdx, dstIdx,
                vB + (size_t)OFF_[s] * HID,
                M_rel + (size_t)relBase * 512,
                scB, mB, denB, accB, E);

            finalize_kernel<<<cdiv(Nd * HID, 256), 256>>>(
                oB + (size_t)OFF_[d] * HID, accB, denB, Nd * HID);
        }

        // adapter + gated residual per type (tmp o -> accB, which is free now)
        for (int t = 0; t < T_TYPES; t++) {
            int base = l * T_TYPES + t;
            gemm64_kernel<1, 0><<<cdiv(N_[t], 64), 256>>>(
                oB + (size_t)OFF_[t] * HID, AW + (size_t)base * 4096,
                Ab + (size_t)base * 64, accB, N_[t], HID);
            combine_kernel<<<cdiv(N_[t] * HID, 256), 256>>>(
                hB + (size_t)OFF_[t] * HID, accB, skip, base, N_[t] * HID);
        }
    }

    // final head on author nodes
    out_kernel<<<cdiv(N_[0], 256), 256>>>(hB, W_out, b_out, (float*)d_out, N_[0]);
}

// round 3
// speedup vs baseline: 1.5912x; 1.5912x over previous
#include <cuda_runtime.h>
#include <cuda_bf16.h>
#include <math.h>

// ---------------- problem constants ----------------
#define T_TYPES 4
#define R_RELS 6
#define HID 64
#define HEADS 8
#define DH 8
#define LAYERS 2
#define OUT_DIM 4

static const int N_[T_TYPES]   = {100000, 200000, 20000, 2000};
static const int F_[T_TYPES]   = {334, 512, 128, 128};
static const int OFF_[T_TYPES] = {0, 100000, 300000, 320000};
#define NTOT 322000
static const int E_[R_RELS]  = {800000, 800000, 1000000, 1000000, 200000, 200000};
static const int RS_[R_RELS] = {0, 1, 1, 2, 1, 3};   // src type
static const int RD_[R_RELS] = {1, 0, 2, 1, 3, 1};   // dst type

// per-relation scratch segmentation (dst-local node counts)
static const int CUMND_[R_RELS + 1] = {0, 200000, 300000, 320000, 520000, 522000, 722000};
static const int CUME_[R_RELS + 1]  = {0, 800000, 1600000, 2600000, 3600000, 3800000, 4000000};
#define NDSUM 722000
#define ESUM  4000000

// blocks per relation for edge passes (32 edges / block)
static const int BLKOFF_[R_RELS + 1] = {0, 25000, 50000, 81250, 112500, 118750, 125000};
#define EDGE_BLOCKS 125000

// ---------------- device scratch (static, no allocation) ----------------
__device__ float    g_h[NTOT * HID];
__device__ float    g_K[NTOT * HID];
__device__ float    g_Q[NTOT * HID];
__device__ float    g_V[NTOT * HID];
__device__ float    g_acc[NDSUM * HID];
__device__ float    g_den[NDSUM * HEADS];
__device__ unsigned g_m[NDSUM * HEADS];
__device__ float    g_sc[ESUM * HEADS];

// ---------------- helpers ----------------
__device__ __forceinline__ unsigned fOrd(float f) {
    unsigned u = __float_as_uint(f);
    return (u & 0x80000000u) ? ~u : (u | 0x80000000u);
}
__device__ __forceinline__ float ordF(unsigned u) {
    return (u & 0x80000000u) ? __uint_as_float(u ^ 0x80000000u) : __uint_as_float(~u);
}
#define ORD_NEG_INF 0x007FFFFFu

__device__ __forceinline__ float gelu_exact(float x) {
    return 0.5f * x * (1.0f + erff(x * 0.70710678118654752f));
}

__device__ __forceinline__ void redAdd4(float* p, float4 v) {
    asm volatile("red.global.add.v4.f32 [%0], {%1,%2,%3,%4};"
                 :: "l"(p), "f"(v.x), "f"(v.y), "f"(v.z), "f"(v.w) : "memory");
}

// ---------------- fill kernels (vectorized, grid-stride) ----------------
__global__ void fill4_f32(float4* p, float v, int n4) {
    int i = blockIdx.x * blockDim.x + threadIdx.x;
    float4 val = make_float4(v, v, v, v);
    for (; i < n4; i += gridDim.x * blockDim.x) p[i] = val;
}
__global__ void fill4_u32(uint4* p, unsigned v, int n4) {
    int i = blockIdx.x * blockDim.x + threadIdx.x;
    uint4 val = make_uint4(v, v, v, v);
    for (; i < n4; i += gridDim.x * blockDim.x) p[i] = val;
}

// ---------------- generic tiled GEMM (input projections): Y = relu(X@W + B) ----------------
__global__ void gemm64_kernel(const float* __restrict__ X, const float* __restrict__ W,
                              const float* __restrict__ B, float* __restrict__ Y,
                              int M, int K) {
    __shared__ float xs[64][33];
    __shared__ float ws[32][64];
    int tid = threadIdx.x;
    int tx = tid & 15, ty = tid >> 4;
    int rowBase = blockIdx.x * 64;
    float acc[4][4] = {};
    for (int k0 = 0; k0 < K; k0 += 32) {
        #pragma unroll
        for (int it = 0; it < 8; it++) {
            int idx = tid + it * 256;
            int r = idx >> 5, c = idx & 31;
            int gr = rowBase + r, gc = k0 + c;
            xs[r][c] = (gr < M && gc < K) ? X[(size_t)gr * K + gc] : 0.0f;
        }
        #pragma unroll
        for (int it = 0; it < 8; it++) {
            int idx = tid + it * 256;
            int kk = idx >> 6, c = idx & 63;
            int gk = k0 + kk;
            ws[kk][c] = (gk < K) ? W[(size_t)gk * 64 + c] : 0.0f;
        }
        __syncthreads();
        #pragma unroll
        for (int kk = 0; kk < 32; kk++) {
            float a[4], b[4];
            #pragma unroll
            for (int i = 0; i < 4; i++) a[i] = xs[ty + 16 * i][kk];
            #pragma unroll
            for (int j = 0; j < 4; j++) b[j] = ws[kk][tx + 16 * j];
            #pragma unroll
            for (int i = 0; i < 4; i++)
                #pragma unroll
                for (int j = 0; j < 4; j++)
                    acc[i][j] += a[i] * b[j];
        }
        __syncthreads();
    }
    #pragma unroll
    for (int i = 0; i < 4; i++) {
        int gr = rowBase + ty + 16 * i;
        if (gr >= M) continue;
        #pragma unroll
        for (int j = 0; j < 4; j++) {
            int col = tx + 16 * j;
            float v = acc[i][j] + B[col];
            Y[(size_t)gr * 64 + col] = fmaxf(v, 0.0f);
        }
    }
}

// ---------------- fused K/Q/V projection: K=HID=64, three outputs ----------------
__global__ void gemm_kqv_kernel(const float* __restrict__ X,
                                const float* __restrict__ Wk, const float* __restrict__ Wq,
                                const float* __restrict__ Wv,
                                const float* __restrict__ bk, const float* __restrict__ bq,
                                const float* __restrict__ bv,
                                float* __restrict__ Yk, float* __restrict__ Yq,
                                float* __restrict__ Yv, int M) {
    __shared__ float xs[64][65];
    __shared__ float ws[64][192];
    __shared__ float bs[192];
    int tid = threadIdx.x;
    int rowBase = blockIdx.x * 64;
    #pragma unroll
    for (int it = 0; it < 16; it++) {
        int idx = tid + it * 256;
        int r = idx >> 6, c = idx & 63;
        int gr = rowBase + r;
        xs[r][c] = (gr < M) ? X[(size_t)gr * 64 + c] : 0.0f;
        ws[r][c]       = Wk[idx];
        ws[r][64 + c]  = Wq[idx];
        ws[r][128 + c] = Wv[idx];
    }
    if (tid < 64) { bs[tid] = bk[tid]; bs[64 + tid] = bq[tid]; bs[128 + tid] = bv[tid]; }
    __syncthreads();
    int tx = tid & 15, ty = tid >> 4;
    float acc[4][12] = {};
    #pragma unroll
    for (int k = 0; k < 64; k++) {
        float a[4], b[12];
        #pragma unroll
        for (int i = 0; i < 4; i++) a[i] = xs[ty + 16 * i][k];
        #pragma unroll
        for (int j = 0; j < 12; j++) b[j] = ws[k][tx + 16 * j];
        #pragma unroll
        for (int i = 0; i < 4; i++)
            #pragma unroll
            for (int j = 0; j < 12; j++)
                acc[i][j] += a[i] * b[j];
    }
    #pragma unroll
    for (int i = 0; i < 4; i++) {
        int gr = rowBase + ty + 16 * i;
        if (gr >= M) continue;
        #pragma unroll
        for (int j = 0; j < 4; j++) {
            int col = tx + 16 * j;
            Yk[(size_t)gr * 64 + col] = acc[i][j]     + bs[col];
            Yq[(size_t)gr * 64 + col] = acc[i][j + 4] + bs[64 + col];
            Yv[(size_t)gr * 64 + col] = acc[i][j + 8] + bs[128 + col];
        }
    }
}

// ---------------- fused edge passes across all relations ----------------
struct RelCtx {
    const int* src; const int* dst;
    const float* K; const float* Q; const float* V;
    const float* A; const float* Mm; const float* P;
    float* sc; unsigned* mx; float* den; float* acc;
    int E;
};
struct PassCtx {
    RelCtx rel[R_RELS];
    int blkOff[R_RELS + 1];
};

// pass A: scores + running max (one thread per (edge,head), 32 edges/block)
__global__ void edge_pass_a(PassCtx p) {
    __shared__ float As[512];     // [d][f][h]
    __shared__ float Ps[8];
    int b = blockIdx.x;
    int r = 0;
    #pragma unroll
    for (int i = 1; i < R_RELS; i++) if (b >= p.blkOff[i]) r = i;
    const RelCtx& rc = p.rel[r];
    int tid = threadIdx.x;
    #pragma unroll
    for (int it = 0; it < 2; it++) {
        int i = tid + it * 256;
        int h = i >> 6, d = (i >> 3) & 7, f = i & 7;
        As[d * 64 + f * 8 + h] = rc.A[i];
    }
    if (tid < 8) Ps[tid] = rc.P[tid];
    __syncthreads();

    int e = (b - p.blkOff[r]) * 32 + (tid >> 3);
    int h = tid & 7;
    if (e >= rc.E) return;
    int s = rc.src[e], dd = rc.dst[e];

    const float4* kp = (const float4*)(rc.K + (size_t)s * 64 + h * 8);
    float4 k0 = kp[0], k1 = kp[1];
    const float4* qp = (const float4*)(rc.Q + (size_t)dd * 64 + h * 8);
    float4 q0 = qp[0], q1 = qp[1];
    float kin[8] = {k0.x, k0.y, k0.z, k0.w, k1.x, k1.y, k1.z, k1.w};
    float qin[8] = {q0.x, q0.y, q0.z, q0.w, q1.x, q1.y, q1.z, q1.w};

    float sc = 0.0f;
    #pragma unroll
    for (int f = 0; f < 8; f++) {
        float kf = 0.0f;
        #pragma unroll
        for (int d2 = 0; d2 < 8; d2++) kf += kin[d2] * As[d2 * 64 + f * 8 + h];
        sc += qin[f] * kf;
    }
    sc *= Ps[h] * 0.35355339059327373f;
    rc.sc[(size_t)e * 8 + h] = sc;
    atomicMax(&rc.mx[(size_t)dd * 8 + h], fOrd(sc));
}

// pass B: exp / denom / message accumulate with vector RED
__global__ void edge_pass_b(PassCtx p) {
    __shared__ float Ms[512];     // [d][f][h]
    int b = blockIdx.x;
    int r = 0;
    #pragma unroll
    for (int i = 1; i < R_RELS; i++) if (b >= p.blkOff[i]) r = i;
    const RelCtx& rc = p.rel[r];
    int tid = threadIdx.x;
    #pragma unroll
    for (int it = 0; it < 2; it++) {
        int i = tid + it * 256;
        int h = i >> 6, d = (i >> 3) & 7, f = i & 7;
        Ms[d * 64 + f * 8 + h] = rc.Mm[i];
    }
    __syncthreads();

    int e = (b - p.blkOff[r]) * 32 + (tid >> 3);
    int h = tid & 7;
    if (e >= rc.E) return;
    int s = rc.src[e], dd = rc.dst[e];

    const float4* vp = (const float4*)(rc.V + (size_t)s * 64 + h * 8);
    float4 v0 = vp[0], v1 = vp[1];
    float vin[8] = {v0.x, v0.y, v0.z, v0.w, v1.x, v1.y, v1.z, v1.w};

    float sc = rc.sc[(size_t)e * 8 + h];
    float m = ordF(rc.mx[(size_t)dd * 8 + h]);
    float ex = __expf(sc - m);

    atomicAdd(&rc.den[(size_t)dd * 8 + h], ex);

    float vf[8];
    #pragma unroll
    for (int f = 0; f < 8; f++) {
        float acc = 0.0f;
        #pragma unroll
        for (int d2 = 0; d2 < 8; d2++) acc += vin[d2] * Ms[d2 * 64 + f * 8 + h];
        vf[f] = acc * ex;
    }
    float* ap = rc.acc + (size_t)dd * 64 + h * 8;
    redAdd4(ap,     make_float4(vf[0], vf[1], vf[2], vf[3]));
    redAdd4(ap + 4, make_float4(vf[4], vf[5], vf[6], vf[7]));
}

// ---------------- fused adapter: out = Σ acc/den -> gelu -> @AW+Ab -> gated residual ----------------
__global__ void adapter_kernel(const float* __restrict__ a0, const float* __restrict__ d0,
                               const float* __restrict__ a1, const float* __restrict__ d1,
                               const float* __restrict__ a2, const float* __restrict__ d2,
                               const float* __restrict__ W, const float* __restrict__ B,
                               const float* __restrict__ skip, int skipIdx,
                               float* __restrict__ h, int M) {
    __shared__ float xs[64][65];
    __shared__ float ws[64][64];
    __shared__ float bs[64];
    int tid = threadIdx.x;
    int rowBase = blockIdx.x * 64;
    #pragma unroll
    for (int it = 0; it < 16; it++) {
        int idx = tid + it * 256;
        int r = idx >> 6, c = idx & 63;
        int node = rowBase + r;
        float v = 0.0f;
        if (node < M) {
            float dv = d0[(size_t)node * 8 + (c >> 3)];
            if (dv > 0.0f) v += a0[(size_t)node * 64 + c] / dv;
            if (a1) {
                float dv1 = d1[(size_t)node * 8 + (c >> 3)];
                if (dv1 > 0.0f) v += a1[(size_t)node * 64 + c] / dv1;
            }
            if (a2) {
                float dv2 = d2[(size_t)node * 8 + (c >> 3)];
                if (dv2 > 0.0f) v += a2[(size_t)node * 64 + c] / dv2;
            }
        }
        xs[r][c] = gelu_exact(v);
        ws[r][c] = W[idx];
    }
    if (tid < 64) bs[tid] = B[tid];
    __syncthreads();
    int tx = tid & 15, ty = tid >> 4;
    float acc[4][4] = {};
    #pragma unroll
    for (int k = 0; k < 64; k++) {
        float a[4], b[4];
        #pragma unroll
        for (int i = 0; i < 4; i++) a[i] = xs[ty + 16 * i][k];
        #pragma unroll
        for (int j = 0; j < 4; j++) b[j] = ws[k][tx + 16 * j];
        #pragma unroll
        for (int i = 0; i < 4; i++)
            #pragma unroll
            for (int j = 0; j < 4; j++)
                acc[i][j] += a[i] * b[j];
    }
    float g = 1.0f / (1.0f + __expf(-skip[skipIdx]));
    #pragma unroll
    for (int i = 0; i < 4; i++) {
        int gr = rowBase + ty + 16 * i;
        if (gr >= M) continue;
        #pragma unroll
        for (int j = 0; j < 4; j++) {
            int col = tx + 16 * j;
            size_t o = (size_t)gr * 64 + col;
            h[o] = g * (acc[i][j] + bs[col]) + (1.0f - g) * h[o];
        }
    }
}

// ---------------- final head ----------------
__global__ void out_kernel(const float* __restrict__ h, const float* __restrict__ Wo,
                           const float* __restrict__ bo, float* __restrict__ y, int n) {
    __shared__ float ws[256];
    __shared__ float bs[4];
    if (threadIdx.x < 256) ws[threadIdx.x] = Wo[threadIdx.x];
    if (threadIdx.x < 4) bs[threadIdx.x] = bo[threadIdx.x];
    __syncthreads();
    int node = blockIdx.x * blockDim.x + threadIdx.x;
    if (node >= n) return;
    const float4* hp = (const float4*)(h + (size_t)node * 64);
    float a0 = bs[0], a1 = bs[1], a2 = bs[2], a3 = bs[3];
    #pragma unroll
    for (int i = 0; i < 16; i++) {
        float4 hv = hp[i];
        const float* w = ws + 16 * i;
        a0 += hv.x * w[0]  + hv.y * w[4]  + hv.z * w[8]  + hv.w * w[12];
        a1 += hv.x * w[1]  + hv.y * w[5]  + hv.z * w[9]  + hv.w * w[13];
        a2 += hv.x * w[2]  + hv.y * w[6]  + hv.z * w[10] + hv.w * w[14];
        a3 += hv.x * w[3]  + hv.y * w[7]  + hv.z * w[11] + hv.w * w[15];
    }
    ((float4*)y)[node] = make_float4(a0, a1, a2, a3);
}

// ---------------- host launcher ----------------
static inline int cdiv(int a, int b) { return (a + b - 1) / b; }

extern "C" void kernel_launch(void* const* d_in, const int* in_sizes, int n_in,
                              void* d_out, int out_size) {
    (void)n_in; (void)out_size;

    const float* x[T_TYPES]   = {(const float*)d_in[0], (const float*)d_in[1],
                                 (const float*)d_in[2], (const float*)d_in[3]};
    const float* Win[T_TYPES] = {(const float*)d_in[4], (const float*)d_in[6],
                                 (const float*)d_in[8], (const float*)d_in[10]};
    const float* bin[T_TYPES] = {(const float*)d_in[5], (const float*)d_in[7],
                                 (const float*)d_in[9], (const float*)d_in[11]};

    // dict order (KW,QW,VW,AW,Kb,Qb,Vb,Ab) vs signature order — disambiguate via sizes
    const float *KW, *Kb, *QW, *Qb, *VW, *Vb, *AW, *Ab;
    if (in_sizes[13] > 4096) {
        KW = (const float*)d_in[12]; QW = (const float*)d_in[13];
        VW = (const float*)d_in[14]; AW = (const float*)d_in[15];
        Kb = (const float*)d_in[16]; Qb = (const float*)d_in[17];
        Vb = (const float*)d_in[18]; Ab = (const float*)d_in[19];
    } else {
        KW = (const float*)d_in[12]; Kb = (const float*)d_in[13];
        QW = (const float*)d_in[14]; Qb = (const float*)d_in[15];
        VW = (const float*)d_in[16]; Vb = (const float*)d_in[17];
        AW = (const float*)d_in[18]; Ab = (const float*)d_in[19];
    }
    const float* skip  = (const float*)d_in[20];
    const float* A_rel = (const float*)d_in[21];
    const float* M_rel = (const float*)d_in[22];
    const float* P_rel = (const float*)d_in[23];
    const float* W_out = (const float*)d_in[24];
    const float* b_out = (const float*)d_in[25];
    const int* ei[R_RELS] = {(const int*)d_in[26], (const int*)d_in[27], (const int*)d_in[28],
                             (const int*)d_in[29], (const int*)d_in[30], (const int*)d_in[31]};

    float *hB, *kB, *qB, *vB, *accB, *denB, *scB;
    unsigned* mB;
    cudaGetSymbolAddress((void**)&hB,   g_h);
    cudaGetSymbolAddress((void**)&kB,   g_K);
    cudaGetSymbolAddress((void**)&qB,   g_Q);
    cudaGetSymbolAddress((void**)&vB,   g_V);
    cudaGetSymbolAddress((void**)&accB, g_acc);
    cudaGetSymbolAddress((void**)&denB, g_den);
    cudaGetSymbolAddress((void**)&mB,   g_m);
    cudaGetSymbolAddress((void**)&scB,  g_sc);

    // ---- input projections: h[t] = relu(x @ W_in + b) ----
    for (int t = 0; t < T_TYPES; t++) {
        gemm64_kernel<<<cdiv(N_[t], 64), 256>>>(
            x[t], Win[t], bin[t], hB + (size_t)OFF_[t] * HID, N_[t], F_[t]);
    }

    for (int l = 0; l < LAYERS; l++) {
        // clear per-layer scratch
        fill4_f32<<<2048, 256>>>((float4*)accB, 0.0f, NDSUM * HID / 4);
        fill4_f32<<<1024, 256>>>((float4*)denB, 0.0f, NDSUM * HEADS / 4);
        fill4_u32<<<1024, 256>>>((uint4*)mB, ORD_NEG_INF, NDSUM * HEADS / 4);

        // fused K/Q/V projections per type
        for (int t = 0; t < T_TYPES; t++) {
            int base = l * T_TYPES + t;
            gemm_kqv_kernel<<<cdiv(N_[t], 64), 256>>>(
                hB + (size_t)OFF_[t] * HID,
                KW + (size_t)base * 4096, QW + (size_t)base * 4096, VW + (size_t)base * 4096,
                Kb + (size_t)base * 64,   Qb + (size_t)base * 64,   Vb + (size_t)base * 64,
                kB + (size_t)OFF_[t] * HID, qB + (size_t)OFF_[t] * HID, vB + (size_t)OFF_[t] * HID,
                N_[t]);
        }

        // build pass context
        PassCtx p;
        for (int r = 0; r < R_RELS; r++) {
            int s = RS_[r], d = RD_[r];
            int relBase = l * R_RELS + r;
            p.rel[r].src = ei[r];
            p.rel[r].dst = ei[r] + E_[r];
            p.rel[r].K  = kB + (size_t)OFF_[s] * HID;
            p.rel[r].Q  = qB + (size_t)OFF_[d] * HID;
            p.rel[r].V  = vB + (size_t)OFF_[s] * HID;
            p.rel[r].A  = A_rel + (size_t)relBase * 512;
            p.rel[r].Mm = M_rel + (size_t)relBase * 512;
            p.rel[r].P  = P_rel + (size_t)relBase * 8;
            p.rel[r].sc  = scB  + (size_t)CUME_[r] * HEADS;
            p.rel[r].mx  = mB   + (size_t)CUMND_[r] * HEADS;
            p.rel[r].den = denB + (size_t)CUMND_[r] * HEADS;
            p.rel[r].acc = accB + (size_t)CUMND_[r] * HID;
            p.rel[r].E = E_[r];
        }
        for (int i = 0; i <= R_RELS; i++) p.blkOff[i] = BLKOFF_[i];

        edge_pass_a<<<EDGE_BLOCKS, 256>>>(p);
        edge_pass_b<<<EDGE_BLOCKS, 256>>>(p);

        // fused adapter per type (finalize + gelu + GEMM + gated residual)
        // rels by dst type: author<-{1}, paper<-{0,3,5}, term<-{2}, conf<-{4}
        static const int relsByType[T_TYPES][3] = {{1, -1, -1}, {0, 3, 5}, {2, -1, -1}, {4, -1, -1}};
        for (int t = 0; t < T_TYPES; t++) {
            int base = l * T_TYPES + t;
            const float *a0 = nullptr, *d0 = nullptr, *a1 = nullptr, *d1 = nullptr,
                        *a2 = nullptr, *d2 = nullptr;
            int r0 = relsByType[t][0];
            a0 = accB + (size_t)CUMND_[r0] * HID;
            d0 = denB + (size_t)CUMND_[r0] * HEADS;
            if (relsByType[t][1] >= 0) {
                int r1 = relsByType[t][1];
                a1 = accB + (size_t)CUMND_[r1] * HID;
                d1 = denB + (size_t)CUMND_[r1] * HEADS;
            }
            if (relsByType[t][2] >= 0) {
                int r2 = relsByType[t][2];
                a2 = accB + (size_t)CUMND_[r2] * HID;
                d2 = denB + (size_t)CUMND_[r2] * HEADS;
            }
            adapter_kernel<<<cdiv(N_[t], 64), 256>>>(
                a0, d0, a1, d1, a2, d2,
                AW + (size_t)base * 4096, Ab + (size_t)base * 64,
                skip, base,
                hB + (size_t)OFF_[t] * HID, N_[t]);
        }
    }

    // final head on author nodes
    out_kernel<<<cdiv(N_[0], 256), 256>>>(hB, W_out, b_out, (float*)d_out, N_[0]);
}

// round 4
// speedup vs baseline: 1.5973x; 1.0038x over previous
#include <cuda_runtime.h>
#include <cuda_bf16.h>
#include <math.h>

// ---------------- problem constants ----------------
#define T_TYPES 4
#define R_RELS 6
#define HID 64
#define HEADS 8
#define DH 8
#define LAYERS 2
#define OUT_DIM 4

static const int N_[T_TYPES]   = {100000, 200000, 20000, 2000};
static const int F_[T_TYPES]   = {334, 512, 128, 128};
static const int OFF_[T_TYPES] = {0, 100000, 300000, 320000};
#define NTOT 322000
static const int E_[R_RELS]  = {800000, 800000, 1000000, 1000000, 200000, 200000};
static const int RS_[R_RELS] = {0, 1, 1, 2, 1, 3};   // src type
static const int RD_[R_RELS] = {1, 0, 2, 1, 3, 1};   // dst type

// per-relation scratch segmentation (dst-local node counts, cumulative)
static const int CUMND_[R_RELS + 1] = {0, 200000, 300000, 320000, 520000, 522000, 722000};
#define NDSUM 722000
#define ESUM  4000000

// attention: blocks per relation (32 nodes / block of 256 threads)
static const int ABLK_[R_RELS + 1] = {0, 6250, 9375, 10000, 16250, 16313, 22563};
#define ATTN_BLOCKS 22563

// ---------------- device scratch (static, no allocation) ----------------
__device__ float    g_h[NTOT * HID];
__device__ float    g_K[NTOT * HID];
__device__ float    g_Q[NTOT * HID];
__device__ float    g_V[NTOT * HID];
__device__ float    g_acc[NDSUM * HID];     // per-relation normalized attention output
__device__ unsigned g_cnt[NDSUM];           // CSR degree counts
__device__ int      g_rowptr[NDSUM + 1];    // CSR row pointers (global exclusive scan)
__device__ int      g_cur[NDSUM];           // scatter cursors
__device__ int      g_bsum[512];            // scan block sums
__device__ int      g_srcs[ESUM];           // dst-sorted source node ids

// ---------------- helpers ----------------
__device__ __forceinline__ float gelu_exact(float x) {
    return 0.5f * x * (1.0f + erff(x * 0.70710678118654752f));
}

// ---------------- fill kernels ----------------
__global__ void fill4_u32(uint4* p, unsigned v, int n4) {
    int i = blockIdx.x * blockDim.x + threadIdx.x;
    uint4 val = make_uint4(v, v, v, v);
    for (; i < n4; i += gridDim.x * blockDim.x) p[i] = val;
}

// ---------------- CSR build ----------------
__global__ void count_kernel(const int* __restrict__ dst, unsigned* __restrict__ cnt, int E) {
    int e = blockIdx.x * blockDim.x + threadIdx.x;
    if (e < E) atomicAdd(&cnt[dst[e]], 1u);
}

// scan pass 1: per-block (2048 elements) exclusive scan + block totals
__global__ void scan1_kernel(const unsigned* __restrict__ cnt, int* __restrict__ row,
                             int* __restrict__ bsum, int n) {
    __shared__ int sm[256];
    int tid = threadIdx.x;
    int base = blockIdx.x * 2048 + tid * 8;
    int vals[8];
    int s = 0;
    #pragma unroll
    for (int i = 0; i < 8; i++) {
        int idx = base + i;
        int t = (idx < n) ? (int)cnt[idx] : 0;
        vals[i] = s;          // exclusive within thread
        s += t;
    }
    sm[tid] = s;
    __syncthreads();
    #pragma unroll
    for (int off = 1; off < 256; off <<= 1) {
        int t = (tid >= off) ? sm[tid - off] : 0;
        __syncthreads();
        sm[tid] += t;
        __syncthreads();
    }
    int excl = sm[tid] - s;
    if (tid == 255) bsum[blockIdx.x] = sm[255];
    #pragma unroll
    for (int i = 0; i < 8; i++) {
        int idx = base + i;
        if (idx < n) row[idx] = excl + vals[i];
    }
}

// scan pass 2: single block exclusive scan of block totals (nb <= 512)
__global__ void scan2_kernel(int* __restrict__ bsum, int nb) {
    __shared__ int sm[512];
    int tid = threadIdx.x;
    int v = (tid < nb) ? bsum[tid] : 0;
    sm[tid] = v;
    __syncthreads();
    #pragma unroll
    for (int off = 1; off < 512; off <<= 1) {
        int t = (tid >= off) ? sm[tid - off] : 0;
        __syncthreads();
        sm[tid] += t;
        __syncthreads();
    }
    if (tid < nb) bsum[tid] = sm[tid] - v;   // exclusive
}

// scan pass 3: add block offsets; copy to cursor; set terminator
__global__ void scan3_kernel(int* __restrict__ row, int* __restrict__ cur,
                             const int* __restrict__ bsum, int n, int total) {
    int idx = blockIdx.x * blockDim.x + threadIdx.x;
    if (idx < n) {
        int v = row[idx] + bsum[idx >> 11];
        row[idx] = v;
        cur[idx] = v;
    }
    if (idx == 0) row[n] = total;
}

__global__ void scatter_kernel(const int* __restrict__ src, const int* __restrict__ dst,
                               int* __restrict__ cur, int* __restrict__ srcs, int E) {
    int e = blockIdx.x * blockDim.x + threadIdx.x;
    if (e >= E) return;
    int pos = atomicAdd(&cur[dst[e]], 1);
    srcs[pos] = src[e];
}

// ---------------- input projection GEMM: Y = relu(X[M,K] @ W[K,64] + B), 128-row tiles ----------------
__global__ void gemm_in_kernel(const float* __restrict__ X, const float* __restrict__ W,
                               const float* __restrict__ B, float* __restrict__ Y,
                               int M, int K) {
    __shared__ float xs[128][33];
    __shared__ float ws[32][64];
    int tid = threadIdx.x;
    int tx = tid & 15, ty = tid >> 4;
    int rowBase = blockIdx.x * 128;
    float acc[8][4] = {};
    for (int k0 = 0; k0 < K; k0 += 32) {
        #pragma unroll
        for (int it = 0; it < 16; it++) {
            int idx = tid + it * 256;
            int r = idx >> 5, c = idx & 31;
            int gr = rowBase + r, gc = k0 + c;
            xs[r][c] = (gr < M && gc < K) ? X[(size_t)gr * K + gc] : 0.0f;
        }
        #pragma unroll
        for (int it = 0; it < 8; it++) {
            int idx = tid + it * 256;
            int kk = idx >> 6, c = idx & 63;
            int gk = k0 + kk;
            ws[kk][c] = (gk < K) ? W[(size_t)gk * 64 + c] : 0.0f;
        }
        __syncthreads();
        #pragma unroll
        for (int kk = 0; kk < 32; kk++) {
            float a[8], b[4];
            #pragma unroll
            for (int i = 0; i < 8; i++) a[i] = xs[ty + 16 * i][kk];
            #pragma unroll
            for (int j = 0; j < 4; j++) b[j] = ws[kk][tx + 16 * j];
            #pragma unroll
            for (int i = 0; i < 8; i++)
                #pragma unroll
                for (int j = 0; j < 4; j++)
                    acc[i][j] += a[i] * b[j];
        }
        __syncthreads();
    }
    #pragma unroll
    for (int i = 0; i < 8; i++) {
        int gr = rowBase + ty + 16 * i;
        if (gr >= M) continue;
        #pragma unroll
        for (int j = 0; j < 4; j++) {
            int col = tx + 16 * j;
            Y[(size_t)gr * 64 + col] = fmaxf(acc[i][j] + B[col], 0.0f);
        }
    }
}

// ---------------- fused K/Q/V projection (K=64) ----------------
__global__ void gemm_kqv_kernel(const float* __restrict__ X,
                                const float* __restrict__ Wk, const float* __restrict__ Wq,
                                const float* __restrict__ Wv,
                                const float* __restrict__ bk, const float* __restrict__ bq,
                                const float* __restrict__ bv,
                                float* __restrict__ Yk, float* __restrict__ Yq,
                                float* __restrict__ Yv, int M) {
    __shared__ float xs[64][65];
    __shared__ float ws[64][192];
    __shared__ float bs[192];
    int tid = threadIdx.x;
    int rowBase = blockIdx.x * 64;
    #pragma unroll
    for (int it = 0; it < 16; it++) {
        int idx = tid + it * 256;
        int r = idx >> 6, c = idx & 63;
        int gr = rowBase + r;
        xs[r][c] = (gr < M) ? X[(size_t)gr * 64 + c] : 0.0f;
        ws[r][c]       = Wk[idx];
        ws[r][64 + c]  = Wq[idx];
        ws[r][128 + c] = Wv[idx];
    }
    if (tid < 64) { bs[tid] = bk[tid]; bs[64 + tid] = bq[tid]; bs[128 + tid] = bv[tid]; }
    __syncthreads();
    int tx = tid & 15, ty = tid >> 4;
    float acc[4][12] = {};
    #pragma unroll
    for (int k = 0; k < 64; k++) {
        float a[4], b[12];
        #pragma unroll
        for (int i = 0; i < 4; i++) a[i] = xs[ty + 16 * i][k];
        #pragma unroll
        for (int j = 0; j < 12; j++) b[j] = ws[k][tx + 16 * j];
        #pragma unroll
        for (int i = 0; i < 4; i++)
            #pragma unroll
            for (int j = 0; j < 12; j++)
                acc[i][j] += a[i] * b[j];
    }
    #pragma unroll
    for (int i = 0; i < 4; i++) {
        int gr = rowBase + ty + 16 * i;
        if (gr >= M) continue;
        #pragma unroll
        for (int j = 0; j < 4; j++) {
            int col = tx + 16 * j;
            Yk[(size_t)gr * 64 + col] = acc[i][j]     + bs[col];
            Yq[(size_t)gr * 64 + col] = acc[i][j + 4] + bs[64 + col];
            Yv[(size_t)gr * 64 + col] = acc[i][j + 8] + bs[128 + col];
        }
    }
}

// ---------------- dst-centric online-softmax attention (all relations, one launch) ----------------
struct AttnRel {
    const float *K, *Q, *V, *A, *Mm, *P;
    const int* rowPtr;   // per-relation base into global rowptr
    float* acc;          // per-relation output base
    int Nd;
};
struct AttnCtx {
    AttnRel rel[R_RELS];
    int blkOff[R_RELS + 1];
};

__global__ void attn_kernel(AttnCtx p, const int* __restrict__ srcs) {
    __shared__ float As[512];    // [d][f][h]
    __shared__ float Ms[512];
    __shared__ float Ps[8];
    int b = blockIdx.x;
    int r = 0;
    #pragma unroll
    for (int i = 1; i < R_RELS; i++) if (b >= p.blkOff[i]) r = i;
    const AttnRel rc = p.rel[r];
    int tid = threadIdx.x;
    #pragma unroll
    for (int it = 0; it < 2; it++) {
        int i = tid + it * 256;
        int h = i >> 6, d = (i >> 3) & 7, f = i & 7;
        As[d * 64 + f * 8 + h] = rc.A[i];
        Ms[d * 64 + f * 8 + h] = rc.Mm[i];
    }
    if (tid < 8) Ps[tid] = rc.P[tid];
    __syncthreads();

    int node = (b - p.blkOff[r]) * 32 + (tid >> 3);
    int h = tid & 7;
    if (node >= rc.Nd) return;

    const float4* qp = (const float4*)(rc.Q + (size_t)node * 64 + h * 8);
    float4 q0 = qp[0], q1 = qp[1];
    float q[8] = {q0.x, q0.y, q0.z, q0.w, q1.x, q1.y, q1.z, q1.w};

    int beg = rc.rowPtr[node];
    int end = rc.rowPtr[node + 1];
    float pscale = Ps[h] * 0.35355339059327373f;

    float m = -INFINITY, den = 0.0f;
    float a[8] = {};

    for (int j = beg; j < end; j++) {
        int s = __ldg(&srcs[j]);
        const float4* kp = (const float4*)(rc.K + (size_t)s * 64 + h * 8);
        float4 k0 = kp[0], k1 = kp[1];
        float k[8] = {k0.x, k0.y, k0.z, k0.w, k1.x, k1.y, k1.z, k1.w};
        const float4* vp = (const float4*)(rc.V + (size_t)s * 64 + h * 8);
        float4 v0 = vp[0], v1 = vp[1];
        float v[8] = {v0.x, v0.y, v0.z, v0.w, v1.x, v1.y, v1.z, v1.w};

        float sc = 0.0f;
        #pragma unroll
        for (int f = 0; f < 8; f++) {
            float kf = 0.0f;
            #pragma unroll
            for (int d2 = 0; d2 < 8; d2++) kf += k[d2] * As[d2 * 64 + f * 8 + h];
            sc += q[f] * kf;
        }
        sc *= pscale;

        float mn = fmaxf(m, sc);
        float cOld = __expf(m - mn);     // 0 on first edge (m = -inf)
        float ex = __expf(sc - mn);
        den = den * cOld + ex;
        #pragma unroll
        for (int f = 0; f < 8; f++) {
            float vf = 0.0f;
            #pragma unroll
            for (int d2 = 0; d2 < 8; d2++) vf += v[d2] * Ms[d2 * 64 + f * 8 + h];
            a[f] = a[f] * cOld + ex * vf;
        }
        m = mn;
    }

    float inv = (den > 0.0f) ? 1.0f / den : 0.0f;
    float4* op = (float4*)(rc.acc + (size_t)node * 64 + h * 8);
    op[0] = make_float4(a[0] * inv, a[1] * inv, a[2] * inv, a[3] * inv);
    op[1] = make_float4(a[4] * inv, a[5] * inv, a[6] * inv, a[7] * inv);
}

// ---------------- fused adapter: sum rel outputs -> gelu -> @AW+Ab -> gated residual ----------------
__global__ void adapter_kernel(const float* __restrict__ a0, const float* __restrict__ a1,
                               const float* __restrict__ a2,
                               const float* __restrict__ W, const float* __restrict__ B,
                               const float* __restrict__ skip, int skipIdx,
                               float* __restrict__ h, int M) {
    __shared__ float xs[64][65];
    __shared__ float ws[64][64];
    __shared__ float bs[64];
    int tid = threadIdx.x;
    int rowBase = blockIdx.x * 64;
    #pragma unroll
    for (int it = 0; it < 16; it++) {
        int idx = tid + it * 256;
        int r = idx >> 6, c = idx & 63;
        int node = rowBase + r;
        float v = 0.0f;
        if (node < M) {
            v = a0[(size_t)node * 64 + c];
            if (a1) v += a1[(size_t)node * 64 + c];
            if (a2) v += a2[(size_t)node * 64 + c];
        }
        xs[r][c] = gelu_exact(v);
        ws[r][c] = W[idx];
    }
    if (tid < 64) bs[tid] = B[tid];
    __syncthreads();
    int tx = tid & 15, ty = tid >> 4;
    float acc[4][4] = {};
    #pragma unroll
    for (int k = 0; k < 64; k++) {
        float a[4], b[4];
        #pragma unroll
        for (int i = 0; i < 4; i++) a[i] = xs[ty + 16 * i][k];
        #pragma unroll
        for (int j = 0; j < 4; j++) b[j] = ws[k][tx + 16 * j];
        #pragma unroll
        for (int i = 0; i < 4; i++)
            #pragma unroll
            for (int j = 0; j < 4; j++)
                acc[i][j] += a[i] * b[j];
    }
    float g = 1.0f / (1.0f + __expf(-skip[skipIdx]));
    #pragma unroll
    for (int i = 0; i < 4; i++) {
        int gr = rowBase + ty + 16 * i;
        if (gr >= M) continue;
        #pragma unroll
        for (int j = 0; j < 4; j++) {
            int col = tx + 16 * j;
            size_t o = (size_t)gr * 64 + col;
            h[o] = g * (acc[i][j] + bs[col]) + (1.0f - g) * h[o];
        }
    }
}

// ---------------- final head ----------------
__global__ void out_kernel(const float* __restrict__ h, const float* __restrict__ Wo,
                           const float* __restrict__ bo, float* __restrict__ y, int n) {
    __shared__ float ws[256];
    __shared__ float bs[4];
    if (threadIdx.x < 256) ws[threadIdx.x] = Wo[threadIdx.x];
    if (threadIdx.x < 4) bs[threadIdx.x] = bo[threadIdx.x];
    __syncthreads();
    int node = blockIdx.x * blockDim.x + threadIdx.x;
    if (node >= n) return;
    const float4* hp = (const float4*)(h + (size_t)node * 64);
    float a0 = bs[0], a1 = bs[1], a2 = bs[2], a3 = bs[3];
    #pragma unroll
    for (int i = 0; i < 16; i++) {
        float4 hv = hp[i];
        const float* w = ws + 16 * i;
        a0 += hv.x * w[0]  + hv.y * w[4]  + hv.z * w[8]  + hv.w * w[12];
        a1 += hv.x * w[1]  + hv.y * w[5]  + hv.z * w[9]  + hv.w * w[13];
        a2 += hv.x * w[2]  + hv.y * w[6]  + hv.z * w[10] + hv.w * w[14];
        a3 += hv.x * w[3]  + hv.y * w[7]  + hv.z * w[11] + hv.w * w[15];
    }
    ((float4*)y)[node] = make_float4(a0, a1, a2, a3);
}

// ---------------- host launcher ----------------
static inline int cdiv(int a, int b) { return (a + b - 1) / b; }

extern "C" void kernel_launch(void* const* d_in, const int* in_sizes, int n_in,
                              void* d_out, int out_size) {
    (void)n_in; (void)out_size;

    const float* x[T_TYPES]   = {(const float*)d_in[0], (const float*)d_in[1],
                                 (const float*)d_in[2], (const float*)d_in[3]};
    const float* Win[T_TYPES] = {(const float*)d_in[4], (const float*)d_in[6],
                                 (const float*)d_in[8], (const float*)d_in[10]};
    const float* bin[T_TYPES] = {(const float*)d_in[5], (const float*)d_in[7],
                                 (const float*)d_in[9], (const float*)d_in[11]};

    // dict order (KW,QW,VW,AW,Kb,Qb,Vb,Ab) vs signature order — disambiguate via sizes
    const float *KW, *Kb, *QW, *Qb, *VW, *Vb, *AW, *Ab;
    if (in_sizes[13] > 4096) {
        KW = (const float*)d_in[12]; QW = (const float*)d_in[13];
        VW = (const float*)d_in[14]; AW = (const float*)d_in[15];
        Kb = (const float*)d_in[16]; Qb = (const float*)d_in[17];
        Vb = (const float*)d_in[18]; Ab = (const float*)d_in[19];
    } else {
        KW = (const float*)d_in[12]; Kb = (const float*)d_in[13];
        QW = (const float*)d_in[14]; Qb = (const float*)d_in[15];
        VW = (const float*)d_in[16]; Vb = (const float*)d_in[17];
        AW = (const float*)d_in[18]; Ab = (const float*)d_in[19];
    }
    const float* skip  = (const float*)d_in[20];
    const float* A_rel = (const float*)d_in[21];
    const float* M_rel = (const float*)d_in[22];
    const float* P_rel = (const float*)d_in[23];
    const float* W_out = (const float*)d_in[24];
    const float* b_out = (const float*)d_in[25];
    const int* ei[R_RELS] = {(const int*)d_in[26], (const int*)d_in[27], (const int*)d_in[28],
                             (const int*)d_in[29], (const int*)d_in[30], (const int*)d_in[31]};

    float *hB, *kB, *qB, *vB, *accB;
    unsigned* cntB;
    int *rowB, *curB, *bsumB, *srcsB;
    cudaGetSymbolAddress((void**)&hB,   g_h);
    cudaGetSymbolAddress((void**)&kB,   g_K);
    cudaGetSymbolAddress((void**)&qB,   g_Q);
    cudaGetSymbolAddress((void**)&vB,   g_V);
    cudaGetSymbolAddress((void**)&accB, g_acc);
    cudaGetSymbolAddress((void**)&cntB, g_cnt);
    cudaGetSymbolAddress((void**)&rowB, g_rowptr);
    cudaGetSymbolAddress((void**)&curB, g_cur);
    cudaGetSymbolAddress((void**)&bsumB, g_bsum);
    cudaGetSymbolAddress((void**)&srcsB, g_srcs);

    // ---- CSR build (once per launch; edges constant across layers) ----
    fill4_u32<<<1024, 256>>>((uint4*)cntB, 0u, NDSUM / 4);
    for (int r = 0; r < R_RELS; r++) {
        count_kernel<<<cdiv(E_[r], 256), 256>>>(ei[r] + E_[r], cntB + CUMND_[r], E_[r]);
    }
    int nScanBlocks = cdiv(NDSUM, 2048);   // 353
    scan1_kernel<<<nScanBlocks, 256>>>(cntB, rowB, bsumB, NDSUM);
    scan2_kernel<<<1, 512>>>(bsumB, nScanBlocks);
    scan3_kernel<<<cdiv(NDSUM, 256), 256>>>(rowB, curB, bsumB, NDSUM, ESUM);
    for (int r = 0; r < R_RELS; r++) {
        scatter_kernel<<<cdiv(E_[r], 256), 256>>>(ei[r], ei[r] + E_[r],
                                                  curB + CUMND_[r], srcsB, E_[r]);
    }

    // ---- input projections: h[t] = relu(x @ W_in + b) ----
    for (int t = 0; t < T_TYPES; t++) {
        gemm_in_kernel<<<cdiv(N_[t], 128), 256>>>(
            x[t], Win[t], bin[t], hB + (size_t)OFF_[t] * HID, N_[t], F_[t]);
    }

    for (int l = 0; l < LAYERS; l++) {
        // fused K/Q/V projections per type
        for (int t = 0; t < T_TYPES; t++) {
            int base = l * T_TYPES + t;
            gemm_kqv_kernel<<<cdiv(N_[t], 64), 256>>>(
                hB + (size_t)OFF_[t] * HID,
                KW + (size_t)base * 4096, QW + (size_t)base * 4096, VW + (size_t)base * 4096,
                Kb + (size_t)base * 64,   Qb + (size_t)base * 64,   Vb + (size_t)base * 64,
                kB + (size_t)OFF_[t] * HID, qB + (size_t)OFF_[t] * HID, vB + (size_t)OFF_[t] * HID,
                N_[t]);
        }

        // attention over all relations, one launch
        AttnCtx p;
        for (int r = 0; r < R_RELS; r++) {
            int s = RS_[r], d = RD_[r];
            int relBase = l * R_RELS + r;
            p.rel[r].K  = kB + (size_t)OFF_[s] * HID;
            p.rel[r].Q  = qB + (size_t)OFF_[d] * HID;
            p.rel[r].V  = vB + (size_t)OFF_[s] * HID;
            p.rel[r].A  = A_rel + (size_t)relBase * 512;
            p.rel[r].Mm = M_rel + (size_t)relBase * 512;
            p.rel[r].P  = P_rel + (size_t)relBase * 8;
            p.rel[r].rowPtr = rowB + CUMND_[r];
            p.rel[r].acc = accB + (size_t)CUMND_[r] * HID;
            p.rel[r].Nd = N_[d];
        }
        for (int i = 0; i <= R_RELS; i++) p.blkOff[i] = ABLK_[i];
        attn_kernel<<<ATTN_BLOCKS, 256>>>(p, srcsB);

        // fused adapter per type; rels by dst type: author<-{1}, paper<-{0,3,5}, term<-{2}, conf<-{4}
        static const int relsByType[T_TYPES][3] = {{1, -1, -1}, {0, 3, 5}, {2, -1, -1}, {4, -1, -1}};
        for (int t = 0; t < T_TYPES; t++) {
            int base = l * T_TYPES + t;
            const float *a0 = accB + (size_t)CUMND_[relsByType[t][0]] * HID;
            const float *a1 = (relsByType[t][1] >= 0) ? accB + (size_t)CUMND_[relsByType[t][1]] * HID : nullptr;
            const float *a2 = (relsByType[t][2] >= 0) ? accB + (size_t)CUMND_[relsByType[t][2]] * HID : nullptr;
            adapter_kernel<<<cdiv(N_[t], 64), 256>>>(
                a0, a1, a2,
                AW + (size_t)base * 4096, Ab + (size_t)base * 64,
                skip, base,
                hB + (size_t)OFF_[t] * HID, N_[t]);
        }
    }

    // final head on author nodes
    out_kernel<<<cdiv(N_[0], 256), 256>>>(hB, W_out, b_out, (float*)d_out, N_[0]);
}

// round 5
// speedup vs baseline: 2.2327x; 1.3978x over previous
#include <cuda_runtime.h>
#include <cuda_bf16.h>
#include <math.h>

// ---------------- problem constants ----------------
#define T_TYPES 4
#define R_RELS 6
#define HID 64
#define HEADS 8
#define DH 8
#define LAYERS 2
#define OUT_DIM 4

static const int N_[T_TYPES]   = {100000, 200000, 20000, 2000};
static const int F_[T_TYPES]   = {334, 512, 128, 128};
static const int OFF_[T_TYPES] = {0, 100000, 300000, 320000};
#define NTOT 322000
static const int E_[R_RELS]  = {800000, 800000, 1000000, 1000000, 200000, 200000};
static const int RS_[R_RELS] = {0, 1, 1, 2, 1, 3};   // src type
static const int RD_[R_RELS] = {1, 0, 2, 1, 3, 1};   // dst type

// per-relation dst segmentation (cumulative)
static const int CUMND_[R_RELS + 1] = {0, 200000, 300000, 320000, 520000, 522000, 722000};
#define NDSUM 722000
// per-relation src segmentation (cumulative)
static const int CUMSRC_[R_RELS + 1] = {0, 100000, 300000, 500000, 520000, 720000, 722000};
#define SRCSUM 722000
#define ESUM  4000000

// attention: blocks per relation (32 dst nodes / block)
static const int ABLK_[R_RELS + 1] = {0, 6250, 9375, 10000, 16250, 16313, 22563};
#define ATTN_BLOCKS 22563
// transform: blocks per relation (32 src nodes / block)
static const int TBLK_[R_RELS + 1] = {0, 3125, 9375, 15625, 16250, 22500, 22563};
#define TRANS_BLOCKS 22563

// ---------------- device scratch (static, no allocation) ----------------
__device__ float    g_h[NTOT * HID];
__device__ float    g_K[NTOT * HID];
__device__ float    g_Q[NTOT * HID];
__device__ float    g_V[NTOT * HID];
__device__ float    g_Kt[SRCSUM * HID];     // per-relation transformed K (P*scale folded)
__device__ float    g_Vt[SRCSUM * HID];     // per-relation transformed V
__device__ float    g_acc[NDSUM * HID];     // per-relation normalized attention output
__device__ unsigned g_cnt[NDSUM];
__device__ int      g_rowptr[NDSUM + 1];
__device__ int      g_cur[NDSUM];
__device__ int      g_bsum[512];
__device__ int      g_srcs[ESUM];

// ---------------- helpers ----------------
__device__ __forceinline__ float gelu_exact(float x) {
    return 0.5f * x * (1.0f + erff(x * 0.70710678118654752f));
}

__global__ void fill4_u32(uint4* p, unsigned v, int n4) {
    int i = blockIdx.x * blockDim.x + threadIdx.x;
    uint4 val = make_uint4(v, v, v, v);
    for (; i < n4; i += gridDim.x * blockDim.x) p[i] = val;
}

// ---------------- CSR build ----------------
__global__ void count_kernel(const int* __restrict__ dst, unsigned* __restrict__ cnt, int E) {
    int e = blockIdx.x * blockDim.x + threadIdx.x;
    if (e < E) atomicAdd(&cnt[dst[e]], 1u);
}

__global__ void scan1_kernel(const unsigned* __restrict__ cnt, int* __restrict__ row,
                             int* __restrict__ bsum, int n) {
    __shared__ int sm[256];
    int tid = threadIdx.x;
    int base = blockIdx.x * 2048 + tid * 8;
    int vals[8];
    int s = 0;
    #pragma unroll
    for (int i = 0; i < 8; i++) {
        int idx = base + i;
        int t = (idx < n) ? (int)cnt[idx] : 0;
        vals[i] = s;
        s += t;
    }
    sm[tid] = s;
    __syncthreads();
    #pragma unroll
    for (int off = 1; off < 256; off <<= 1) {
        int t = (tid >= off) ? sm[tid - off] : 0;
        __syncthreads();
        sm[tid] += t;
        __syncthreads();
    }
    int excl = sm[tid] - s;
    if (tid == 255) bsum[blockIdx.x] = sm[255];
    #pragma unroll
    for (int i = 0; i < 8; i++) {
        int idx = base + i;
        if (idx < n) row[idx] = excl + vals[i];
    }
}

__global__ void scan2_kernel(int* __restrict__ bsum, int nb) {
    __shared__ int sm[512];
    int tid = threadIdx.x;
    int v = (tid < nb) ? bsum[tid] : 0;
    sm[tid] = v;
    __syncthreads();
    #pragma unroll
    for (int off = 1; off < 512; off <<= 1) {
        int t = (tid >= off) ? sm[tid - off] : 0;
        __syncthreads();
        sm[tid] += t;
        __syncthreads();
    }
    if (tid < nb) bsum[tid] = sm[tid] - v;
}

__global__ void scan3_kernel(int* __restrict__ row, int* __restrict__ cur,
                             const int* __restrict__ bsum, int n, int total) {
    int idx = blockIdx.x * blockDim.x + threadIdx.x;
    if (idx < n) {
        int v = row[idx] + bsum[idx >> 11];
        row[idx] = v;
        cur[idx] = v;
    }
    if (idx == 0) row[n] = total;
}

__global__ void scatter_kernel(const int* __restrict__ src, const int* __restrict__ dst,
                               int* __restrict__ cur, int* __restrict__ srcs, int E) {
    int e = blockIdx.x * blockDim.x + threadIdx.x;
    if (e >= E) return;
    int pos = atomicAdd(&cur[dst[e]], 1);
    srcs[pos] = src[e];
}

// ---------------- input projection GEMM: Y = relu(X[M,K] @ W[K,64] + B) ----------------
__global__ void gemm_in_kernel(const float* __restrict__ X, const float* __restrict__ W,
                               const float* __restrict__ B, float* __restrict__ Y,
                               int M, int K) {
    __shared__ float xs[128][33];
    __shared__ float ws[32][64];
    int tid = threadIdx.x;
    int tx = tid & 15, ty = tid >> 4;
    int rowBase = blockIdx.x * 128;
    float acc[8][4] = {};
    for (int k0 = 0; k0 < K; k0 += 32) {
        #pragma unroll
        for (int it = 0; it < 16; it++) {
            int idx = tid + it * 256;
            int r = idx >> 5, c = idx & 31;
            int gr = rowBase + r, gc = k0 + c;
            xs[r][c] = (gr < M && gc < K) ? X[(size_t)gr * K + gc] : 0.0f;
        }
        #pragma unroll
        for (int it = 0; it < 8; it++) {
            int idx = tid + it * 256;
            int kk = idx >> 6, c = idx & 63;
            int gk = k0 + kk;
            ws[kk][c] = (gk < K) ? W[(size_t)gk * 64 + c] : 0.0f;
        }
        __syncthreads();
        #pragma unroll
        for (int kk = 0; kk < 32; kk++) {
            float a[8], b[4];
            #pragma unroll
            for (int i = 0; i < 8; i++) a[i] = xs[ty + 16 * i][kk];
            #pragma unroll
            for (int j = 0; j < 4; j++) b[j] = ws[kk][tx + 16 * j];
            #pragma unroll
            for (int i = 0; i < 8; i++)
                #pragma unroll
                for (int j = 0; j < 4; j++)
                    acc[i][j] += a[i] * b[j];
        }
        __syncthreads();
    }
    #pragma unroll
    for (int i = 0; i < 8; i++) {
        int gr = rowBase + ty + 16 * i;
        if (gr >= M) continue;
        #pragma unroll
        for (int j = 0; j < 4; j++) {
            int col = tx + 16 * j;
            Y[(size_t)gr * 64 + col] = fmaxf(acc[i][j] + B[col], 0.0f);
        }
    }
}

// ---------------- fused K/Q/V projection (K=64) ----------------
__global__ void gemm_kqv_kernel(const float* __restrict__ X,
                                const float* __restrict__ Wk, const float* __restrict__ Wq,
                                const float* __restrict__ Wv,
                                const float* __restrict__ bk, const float* __restrict__ bq,
                                const float* __restrict__ bv,
                                float* __restrict__ Yk, float* __restrict__ Yq,
                                float* __restrict__ Yv, int M) {
    __shared__ float xs[64][65];
    __shared__ float ws[64][192];
    __shared__ float bs[192];
    int tid = threadIdx.x;
    int rowBase = blockIdx.x * 64;
    #pragma unroll
    for (int it = 0; it < 16; it++) {
        int idx = tid + it * 256;
        int r = idx >> 6, c = idx & 63;
        int gr = rowBase + r;
        xs[r][c] = (gr < M) ? X[(size_t)gr * 64 + c] : 0.0f;
        ws[r][c]       = Wk[idx];
        ws[r][64 + c]  = Wq[idx];
        ws[r][128 + c] = Wv[idx];
    }
    if (tid < 64) { bs[tid] = bk[tid]; bs[64 + tid] = bq[tid]; bs[128 + tid] = bv[tid]; }
    __syncthreads();
    int tx = tid & 15, ty = tid >> 4;
    float acc[4][12] = {};
    #pragma unroll
    for (int k = 0; k < 64; k++) {
        float a[4], b[12];
        #pragma unroll
        for (int i = 0; i < 4; i++) a[i] = xs[ty + 16 * i][k];
        #pragma unroll
        for (int j = 0; j < 12; j++) b[j] = ws[k][tx + 16 * j];
        #pragma unroll
        for (int i = 0; i < 4; i++)
            #pragma unroll
            for (int j = 0; j < 12; j++)
                acc[i][j] += a[i] * b[j];
    }
    #pragma unroll
    for (int i = 0; i < 4; i++) {
        int gr = rowBase + ty + 16 * i;
        if (gr >= M) continue;
        #pragma unroll
        for (int j = 0; j < 4; j++) {
            int col = tx + 16 * j;
            Yk[(size_t)gr * 64 + col] = acc[i][j]     + bs[col];
            Yq[(size_t)gr * 64 + col] = acc[i][j + 4] + bs[64 + col];
            Yv[(size_t)gr * 64 + col] = acc[i][j + 8] + bs[128 + col];
        }
    }
}

// ---------------- per-relation K/V transform: k~ = (k @ A)·P·scale, v~ = v @ M ----------------
struct TransRel {
    const float *K, *V, *A, *Mm, *P;
    float *Kt, *Vt;
    int Nsrc;
};
struct TransCtx {
    TransRel rel[R_RELS];
    int blkOff[R_RELS + 1];
};

__global__ void transform_kernel(TransCtx p) {
    __shared__ float As[512];   // [d*8+f][h] layout -> index d*64 + f*8 + h
    __shared__ float Ms[512];
    __shared__ float Ps[8];
    int b = blockIdx.x;
    int r = 0;
    #pragma unroll
    for (int i = 1; i < R_RELS; i++) if (b >= p.blkOff[i]) r = i;
    const TransRel rc = p.rel[r];
    int tid = threadIdx.x;
    #pragma unroll
    for (int it = 0; it < 2; it++) {
        int i = tid + it * 256;
        int h = i >> 6, d = (i >> 3) & 7, f = i & 7;
        As[d * 64 + f * 8 + h] = rc.A[i];
        Ms[d * 64 + f * 8 + h] = rc.Mm[i];
    }
    if (tid < 8) Ps[tid] = rc.P[tid];
    __syncthreads();

    int node = (b - p.blkOff[r]) * 32 + (tid >> 3);
    int h = tid & 7;
    if (node >= rc.Nsrc) return;

    const float4* kp = (const float4*)(rc.K + (size_t)node * 64 + h * 8);
    float4 k0 = kp[0], k1 = kp[1];
    float k[8] = {k0.x, k0.y, k0.z, k0.w, k1.x, k1.y, k1.z, k1.w};
    const float4* vp = (const float4*)(rc.V + (size_t)node * 64 + h * 8);
    float4 v0 = vp[0], v1 = vp[1];
    float v[8] = {v0.x, v0.y, v0.z, v0.w, v1.x, v1.y, v1.z, v1.w};

    float ps = Ps[h] * 0.35355339059327373f;
    float kt[8], vt[8];
    #pragma unroll
    for (int f = 0; f < 8; f++) {
        float ka = 0.0f, va = 0.0f;
        #pragma unroll
        for (int d = 0; d < 8; d++) {
            ka += k[d] * As[d * 64 + f * 8 + h];
            va += v[d] * Ms[d * 64 + f * 8 + h];
        }
        kt[f] = ka * ps;
        vt[f] = va;
    }
    float4* ko = (float4*)(rc.Kt + (size_t)node * 64 + h * 8);
    ko[0] = make_float4(kt[0], kt[1], kt[2], kt[3]);
    ko[1] = make_float4(kt[4], kt[5], kt[6], kt[7]);
    float4* vo = (float4*)(rc.Vt + (size_t)node * 64 + h * 8);
    vo[0] = make_float4(vt[0], vt[1], vt[2], vt[3]);
    vo[1] = make_float4(vt[4], vt[5], vt[6], vt[7]);
}

// ---------------- dst-centric online-softmax attention ----------------
struct AttnRel {
    const float *Kt, *Q, *Vt;
    const int* rowPtr;
    float* acc;
    int Nd;
};
struct AttnCtx {
    AttnRel rel[R_RELS];
    int blkOff[R_RELS + 1];
};

__global__ void attn_kernel(AttnCtx p, const int* __restrict__ srcs) {
    int b = blockIdx.x;
    int r = 0;
    #pragma unroll
    for (int i = 1; i < R_RELS; i++) if (b >= p.blkOff[i]) r = i;
    const AttnRel rc = p.rel[r];
    int tid = threadIdx.x;

    int node = (b - p.blkOff[r]) * 32 + (tid >> 3);
    int h = tid & 7;
    if (node >= rc.Nd) return;

    const float4* qp = (const float4*)(rc.Q + (size_t)node * 64 + h * 8);
    float4 q0 = qp[0], q1 = qp[1];
    float q[8] = {q0.x, q0.y, q0.z, q0.w, q1.x, q1.y, q1.z, q1.w};

    int beg = rc.rowPtr[node];
    int end = rc.rowPtr[node + 1];

    float m = -INFINITY, den = 0.0f;
    float a[8] = {};

    #pragma unroll 2
    for (int j = beg; j < end; j++) {
        int s = __ldg(&srcs[j]);
        const float4* kp = (const float4*)(rc.Kt + (size_t)s * 64 + h * 8);
        float4 k0 = kp[0], k1 = kp[1];
        const float4* vp = (const float4*)(rc.Vt + (size_t)s * 64 + h * 8);
        float4 v0 = vp[0], v1 = vp[1];

        float sc = q[0] * k0.x + q[1] * k0.y + q[2] * k0.z + q[3] * k0.w
                 + q[4] * k1.x + q[5] * k1.y + q[6] * k1.z + q[7] * k1.w;

        float mn = fmaxf(m, sc);
        float cOld = __expf(m - mn);
        float ex = __expf(sc - mn);
        den = den * cOld + ex;
        a[0] = a[0] * cOld + ex * v0.x;
        a[1] = a[1] * cOld + ex * v0.y;
        a[2] = a[2] * cOld + ex * v0.z;
        a[3] = a[3] * cOld + ex * v0.w;
        a[4] = a[4] * cOld + ex * v1.x;
        a[5] = a[5] * cOld + ex * v1.y;
        a[6] = a[6] * cOld + ex * v1.z;
        a[7] = a[7] * cOld + ex * v1.w;
        m = mn;
    }

    float inv = (den > 0.0f) ? 1.0f / den : 0.0f;
    float4* op = (float4*)(rc.acc + (size_t)node * 64 + h * 8);
    op[0] = make_float4(a[0] * inv, a[1] * inv, a[2] * inv, a[3] * inv);
    op[1] = make_float4(a[4] * inv, a[5] * inv, a[6] * inv, a[7] * inv);
}

// ---------------- fused adapter: sum rel outputs -> gelu -> @AW+Ab -> gated residual ----------------
__global__ void adapter_kernel(const float* __restrict__ a0, const float* __restrict__ a1,
                               const float* __restrict__ a2,
                               const float* __restrict__ W, const float* __restrict__ B,
                               const float* __restrict__ skip, int skipIdx,
                               float* __restrict__ h, int M) {
    __shared__ float xs[64][65];
    __shared__ float ws[64][64];
    __shared__ float bs[64];
    int tid = threadIdx.x;
    int rowBase = blockIdx.x * 64;
    #pragma unroll
    for (int it = 0; it < 16; it++) {
        int idx = tid + it * 256;
        int r = idx >> 6, c = idx & 63;
        int node = rowBase + r;
        float v = 0.0f;
        if (node < M) {
            v = a0[(size_t)node * 64 + c];
            if (a1) v += a1[(size_t)node * 64 + c];
            if (a2) v += a2[(size_t)node * 64 + c];
        }
        xs[r][c] = gelu_exact(v);
        ws[r][c] = W[idx];
    }
    if (tid < 64) bs[tid] = B[tid];
    __syncthreads();
    int tx = tid & 15, ty = tid >> 4;
    float acc[4][4] = {};
    #pragma unroll
    for (int k = 0; k < 64; k++) {
        float a[4], b[4];
        #pragma unroll
        for (int i = 0; i < 4; i++) a[i] = xs[ty + 16 * i][k];
        #pragma unroll
        for (int j = 0; j < 4; j++) b[j] = ws[k][tx + 16 * j];
        #pragma unroll
        for (int i = 0; i < 4; i++)
            #pragma unroll
            for (int j = 0; j < 4; j++)
                acc[i][j] += a[i] * b[j];
    }
    float g = 1.0f / (1.0f + __expf(-skip[skipIdx]));
    #pragma unroll
    for (int i = 0; i < 4; i++) {
        int gr = rowBase + ty + 16 * i;
        if (gr >= M) continue;
        #pragma unroll
        for (int j = 0; j < 4; j++) {
            int col = tx + 16 * j;
            size_t o = (size_t)gr * 64 + col;
            h[o] = g * (acc[i][j] + bs[col]) + (1.0f - g) * h[o];
        }
    }
}

// ---------------- final head ----------------
__global__ void out_kernel(const float* __restrict__ h, const float* __restrict__ Wo,
                           const float* __restrict__ bo, float* __restrict__ y, int n) {
    __shared__ float ws[256];
    __shared__ float bs[4];
    if (threadIdx.x < 256) ws[threadIdx.x] = Wo[threadIdx.x];
    if (threadIdx.x < 4) bs[threadIdx.x] = bo[threadIdx.x];
    __syncthreads();
    int node = blockIdx.x * blockDim.x + threadIdx.x;
    if (node >= n) return;
    const float4* hp = (const float4*)(h + (size_t)node * 64);
    float a0 = bs[0], a1 = bs[1], a2 = bs[2], a3 = bs[3];
    #pragma unroll
    for (int i = 0; i < 16; i++) {
        float4 hv = hp[i];
        const float* w = ws + 16 * i;
        a0 += hv.x * w[0]  + hv.y * w[4]  + hv.z * w[8]  + hv.w * w[12];
        a1 += hv.x * w[1]  + hv.y * w[5]  + hv.z * w[9]  + hv.w * w[13];
        a2 += hv.x * w[2]  + hv.y * w[6]  + hv.z * w[10] + hv.w * w[14];
        a3 += hv.x * w[3]  + hv.y * w[7]  + hv.z * w[11] + hv.w * w[15];
    }
    ((float4*)y)[node] = make_float4(a0, a1, a2, a3);
}

// ---------------- host launcher ----------------
static inline int cdiv(int a, int b) { return (a + b - 1) / b; }

extern "C" void kernel_launch(void* const* d_in, const int* in_sizes, int n_in,
                              void* d_out, int out_size) {
    (void)n_in; (void)out_size;

    const float* x[T_TYPES]   = {(const float*)d_in[0], (const float*)d_in[1],
                                 (const float*)d_in[2], (const float*)d_in[3]};
    const float* Win[T_TYPES] = {(const float*)d_in[4], (const float*)d_in[6],
                                 (const float*)d_in[8], (const float*)d_in[10]};
    const float* bin[T_TYPES] = {(const float*)d_in[5], (const float*)d_in[7],
                                 (const float*)d_in[9], (const float*)d_in[11]};

    const float *KW, *Kb, *QW, *Qb, *VW, *Vb, *AW, *Ab;
    if (in_sizes[13] > 4096) {
        KW = (const float*)d_in[12]; QW = (const float*)d_in[13];
        VW = (const float*)d_in[14]; AW = (const float*)d_in[15];
        Kb = (const float*)d_in[16]; Qb = (const float*)d_in[17];
        Vb = (const float*)d_in[18]; Ab = (const float*)d_in[19];
    } else {
        KW = (const float*)d_in[12]; Kb = (const float*)d_in[13];
        QW = (const float*)d_in[14]; Qb = (const float*)d_in[15];
        VW = (const float*)d_in[16]; Vb = (const float*)d_in[17];
        AW = (const float*)d_in[18]; Ab = (const float*)d_in[19];
    }
    const float* skip  = (const float*)d_in[20];
    const float* A_rel = (const float*)d_in[21];
    const float* M_rel = (const float*)d_in[22];
    const float* P_rel = (const float*)d_in[23];
    const float* W_out = (const float*)d_in[24];
    const float* b_out = (const float*)d_in[25];
    const int* ei[R_RELS] = {(const int*)d_in[26], (const int*)d_in[27], (const int*)d_in[28],
                             (const int*)d_in[29], (const int*)d_in[30], (const int*)d_in[31]};

    float *hB, *kB, *qB, *vB, *ktB, *vtB, *accB;
    unsigned* cntB;
    int *rowB, *curB, *bsumB, *srcsB;
    cudaGetSymbolAddress((void**)&hB,   g_h);
    cudaGetSymbolAddress((void**)&kB,   g_K);
    cudaGetSymbolAddress((void**)&qB,   g_Q);
    cudaGetSymbolAddress((void**)&vB,   g_V);
    cudaGetSymbolAddress((void**)&ktB,  g_Kt);
    cudaGetSymbolAddress((void**)&vtB,  g_Vt);
    cudaGetSymbolAddress((void**)&accB, g_acc);
    cudaGetSymbolAddress((void**)&cntB, g_cnt);
    cudaGetSymbolAddress((void**)&rowB, g_rowptr);
    cudaGetSymbolAddress((void**)&curB, g_cur);
    cudaGetSymbolAddress((void**)&bsumB, g_bsum);
    cudaGetSymbolAddress((void**)&srcsB, g_srcs);

    // ---- CSR build (once; edge lists constant across layers) ----
    fill4_u32<<<1024, 256>>>((uint4*)cntB, 0u, NDSUM / 4);
    for (int r = 0; r < R_RELS; r++) {
        count_kernel<<<cdiv(E_[r], 256), 256>>>(ei[r] + E_[r], cntB + CUMND_[r], E_[r]);
    }
    int nScanBlocks = cdiv(NDSUM, 2048);
    scan1_kernel<<<nScanBlocks, 256>>>(cntB, rowB, bsumB, NDSUM);
    scan2_kernel<<<1, 512>>>(bsumB, nScanBlocks);
    scan3_kernel<<<cdiv(NDSUM, 256), 256>>>(rowB, curB, bsumB, NDSUM, ESUM);
    for (int r = 0; r < R_RELS; r++) {
        scatter_kernel<<<cdiv(E_[r], 256), 256>>>(ei[r], ei[r] + E_[r],
                                                  curB + CUMND_[r], srcsB, E_[r]);
    }

    // ---- input projections ----
    for (int t = 0; t < T_TYPES; t++) {
        gemm_in_kernel<<<cdiv(N_[t], 128), 256>>>(
            x[t], Win[t], bin[t], hB + (size_t)OFF_[t] * HID, N_[t], F_[t]);
    }

    for (int l = 0; l < LAYERS; l++) {
        // fused K/Q/V projections per type
        for (int t = 0; t < T_TYPES; t++) {
            int base = l * T_TYPES + t;
            gemm_kqv_kernel<<<cdiv(N_[t], 64), 256>>>(
                hB + (size_t)OFF_[t] * HID,
                KW + (size_t)base * 4096, QW + (size_t)base * 4096, VW + (size_t)base * 4096,
                Kb + (size_t)base * 64,   Qb + (size_t)base * 64,   Vb + (size_t)base * 64,
                kB + (size_t)OFF_[t] * HID, qB + (size_t)OFF_[t] * HID, vB + (size_t)OFF_[t] * HID,
                N_[t]);
        }

        // per-relation K/V transform (hoists A_rel/M_rel/P out of the edge loop)
        TransCtx tp;
        for (int r = 0; r < R_RELS; r++) {
            int s = RS_[r];
            int relBase = l * R_RELS + r;
            tp.rel[r].K  = kB + (size_t)OFF_[s] * HID;
            tp.rel[r].V  = vB + (size_t)OFF_[s] * HID;
            tp.rel[r].A  = A_rel + (size_t)relBase * 512;
            tp.rel[r].Mm = M_rel + (size_t)relBase * 512;
            tp.rel[r].P  = P_rel + (size_t)relBase * 8;
            tp.rel[r].Kt = ktB + (size_t)CUMSRC_[r] * HID;
            tp.rel[r].Vt = vtB + (size_t)CUMSRC_[r] * HID;
            tp.rel[r].Nsrc = N_[s];
        }
        for (int i = 0; i <= R_RELS; i++) tp.blkOff[i] = TBLK_[i];
        transform_kernel<<<TRANS_BLOCKS, 256>>>(tp);

        // attention over all relations, one launch
        AttnCtx p;
        for (int r = 0; r < R_RELS; r++) {
            int d = RD_[r];
            p.rel[r].Kt = ktB + (size_t)CUMSRC_[r] * HID;
            p.rel[r].Q  = qB + (size_t)OFF_[d] * HID;
            p.rel[r].Vt = vtB + (size_t)CUMSRC_[r] * HID;
            p.rel[r].rowPtr = rowB + CUMND_[r];
            p.rel[r].acc = accB + (size_t)CUMND_[r] * HID;
            p.rel[r].Nd = N_[d];
        }
        for (int i = 0; i <= R_RELS; i++) p.blkOff[i] = ABLK_[i];
        attn_kernel<<<ATTN_BLOCKS, 256>>>(p, srcsB);

        // fused adapter per type; rels by dst type: author<-{1}, paper<-{0,3,5}, term<-{2}, conf<-{4}
        static const int relsByType[T_TYPES][3] = {{1, -1, -1}, {0, 3, 5}, {2, -1, -1}, {4, -1, -1}};
        for (int t = 0; t < T_TYPES; t++) {
            int base = l * T_TYPES + t;
            const float *a0 = accB + (size_t)CUMND_[relsByType[t][0]] * HID;
            const float *a1 = (relsByType[t][1] >= 0) ? accB + (size_t)CUMND_[relsByType[t][1]] * HID : nullptr;
            const float *a2 = (relsByType[t][2] >= 0) ? accB + (size_t)CUMND_[relsByType[t][2]] * HID : nullptr;
            adapter_kernel<<<cdiv(N_[t], 64), 256>>>(
                a0, a1, a2,
                AW + (size_t)base * 4096, Ab + (size_t)base * 64,
                skip, base,
                hB + (size_t)OFF_[t] * HID, N_[t]);
        }
    }

    // final head on author nodes
    out_kernel<<<cdiv(N_[0], 256), 256>>>(hB, W_out, b_out, (float*)d_out, N_[0]);
}